// round 1
// baseline (speedup 1.0000x reference)
#include <cuda_runtime.h>
#include <cuda_bf16.h>

// SoftEmbeddedDecisionRules: balanced binary hierarchy over C=1024 classes.
// class_prob[c] = prod over 10 levels of sigmoid((mean_own - mean_sibling)).
// One row (1024 f32) per warp; lane k owns classes [32k, 32k+32).

#define BATCH_N 32768
#define NCLASS 1024

__device__ __forceinline__ float sigmoidf_fast(float x) {
    // e^x / (1 + e^x) = 1 / (1 + e^{-x});  EX2 + RCP, ~few ulp
    return __fdividef(1.0f, 1.0f + __expf(-x));
}

__global__ void __launch_bounds__(256)
soft_tree_kernel(const float* __restrict__ in, float* __restrict__ out) {
    const int warp = (blockIdx.x * blockDim.x + threadIdx.x) >> 5;
    const int lane = threadIdx.x & 31;
    if (warp >= BATCH_N) return;

    const float4* rp = reinterpret_cast<const float4*>(in + (size_t)warp * NCLASS) + lane * 8;

    float4 q[8];
#pragma unroll
    for (int i = 0; i < 8; i++) q[i] = rp[i];

    float v[32];
#pragma unroll
    for (int i = 0; i < 8; i++) {
        v[4 * i + 0] = q[i].x; v[4 * i + 1] = q[i].y;
        v[4 * i + 2] = q[i].z; v[4 * i + 3] = q[i].w;
    }

    // ---- within-lane reduction tree (sums over 2,4,8,16,32 classes) ----
    float s2[16], s4[8], s8[4], s16[2], S;
#pragma unroll
    for (int i = 0; i < 16; i++) s2[i] = v[2 * i] + v[2 * i + 1];
#pragma unroll
    for (int i = 0; i < 8; i++)  s4[i] = s2[2 * i] + s2[2 * i + 1];
#pragma unroll
    for (int i = 0; i < 4; i++)  s8[i] = s4[2 * i] + s4[2 * i + 1];
#pragma unroll
    for (int i = 0; i < 2; i++)  s16[i] = s8[2 * i] + s8[2 * i + 1];
    S = s16[0] + s16[1];

    // ---- cross-lane levels: seg = 32, 64, 128, 256, 512 ----
    // sigmoid((S_own - S_partner)/seg) is exactly this lane's branch prob.
    float F = 1.0f;
    {
        float o;
        o = __shfl_xor_sync(0xffffffffu, S, 1);
        F *= sigmoidf_fast((S - o) * (1.0f / 32.0f));  S += o;
        o = __shfl_xor_sync(0xffffffffu, S, 2);
        F *= sigmoidf_fast((S - o) * (1.0f / 64.0f));  S += o;
        o = __shfl_xor_sync(0xffffffffu, S, 4);
        F *= sigmoidf_fast((S - o) * (1.0f / 128.0f)); S += o;
        o = __shfl_xor_sync(0xffffffffu, S, 8);
        F *= sigmoidf_fast((S - o) * (1.0f / 256.0f)); S += o;
        o = __shfl_xor_sync(0xffffffffu, S, 16);
        F *= sigmoidf_fast((S - o) * (1.0f / 512.0f)); // S += o not needed further
    }

    // ---- within-lane downsweep: seg = 16, 8, 4, 2, 1 ----
    float p16[2];
    {
        float a = sigmoidf_fast((s16[0] - s16[1]) * (1.0f / 16.0f));
        p16[0] = F * a;
        p16[1] = F - p16[0];
    }
    float p8[4];
#pragma unroll
    for (int i = 0; i < 2; i++) {
        float a = sigmoidf_fast((s8[2 * i] - s8[2 * i + 1]) * (1.0f / 8.0f));
        p8[2 * i] = p16[i] * a;
        p8[2 * i + 1] = p16[i] - p8[2 * i];
    }
    float p4[8];
#pragma unroll
    for (int i = 0; i < 4; i++) {
        float a = sigmoidf_fast((s4[2 * i] - s4[2 * i + 1]) * (1.0f / 4.0f));
        p4[2 * i] = p8[i] * a;
        p4[2 * i + 1] = p8[i] - p4[2 * i];
    }
    float p2[16];
#pragma unroll
    for (int i = 0; i < 8; i++) {
        float a = sigmoidf_fast((s2[2 * i] - s2[2 * i + 1]) * (1.0f / 2.0f));
        p2[2 * i] = p4[i] * a;
        p2[2 * i + 1] = p4[i] - p2[2 * i];
    }

    float r[32];
#pragma unroll
    for (int i = 0; i < 16; i++) {
        float a = sigmoidf_fast(v[2 * i] - v[2 * i + 1]);
        float t = p2[i] * a;
        r[2 * i] = t;
        r[2 * i + 1] = p2[i] - t;
    }

    float4* op = reinterpret_cast<float4*>(out + (size_t)warp * NCLASS) + lane * 8;
#pragma unroll
    for (int i = 0; i < 8; i++) {
        float4 w;
        w.x = r[4 * i + 0]; w.y = r[4 * i + 1];
        w.z = r[4 * i + 2]; w.w = r[4 * i + 3];
        op[i] = w;
    }
}

extern "C" void kernel_launch(void* const* d_in, const int* in_sizes, int n_in,
                              void* d_out, int out_size) {
    (void)in_sizes; (void)n_in; (void)out_size;
    const float* in = (const float*)d_in[0];
    float* out = (float*)d_out;
    // 32768 rows, 1 row per warp, 8 warps per block -> 4096 blocks
    soft_tree_kernel<<<BATCH_N / 8, 256>>>(in, out);
}

// round 2
// speedup vs baseline: 1.5725x; 1.5725x over previous
#include <cuda_runtime.h>
#include <cuda_bf16.h>

// SoftEmbeddedDecisionRules: balanced binary hierarchy over C=1024 classes.
// One row (1024 f32) per warp, per-lane-contiguous compute layout (MUFU-minimal),
// with smem-swizzled staging so global loads/stores are fully coalesced.

#define BATCH_N 32768
#define NCLASS 1024
#define WARPS_PER_BLOCK 8

__device__ __forceinline__ float sigmoidf_fast(float x) {
    return __fdividef(1.0f, 1.0f + __expf(-x));
}

// 16B-chunk swizzle: conflict-free for both (c = 32j+lane) and (c = 8*lane+i)
__device__ __forceinline__ int swz(int c) { return c ^ ((c >> 3) & 7); }

__global__ void __launch_bounds__(WARPS_PER_BLOCK * 32)
soft_tree_kernel(const float* __restrict__ in, float* __restrict__ out) {
    __shared__ float4 buf[WARPS_PER_BLOCK][256];

    const int wib  = threadIdx.x >> 5;
    const int lane = threadIdx.x & 31;
    const int row  = blockIdx.x * WARPS_PER_BLOCK + wib;

    const float4* gin = reinterpret_cast<const float4*>(in + (size_t)row * NCLASS);

    // ---- coalesced load -> swizzled smem ----
    float4 t[8];
#pragma unroll
    for (int j = 0; j < 8; j++) t[j] = gin[j * 32 + lane];
#pragma unroll
    for (int j = 0; j < 8; j++) {
        int c = j * 32 + lane;
        buf[wib][swz(c)] = t[j];
    }
    __syncwarp();

    // ---- per-lane-contiguous read from smem (conflict-free via swizzle) ----
    float v[32];
#pragma unroll
    for (int i = 0; i < 8; i++) {
        float4 q = buf[wib][swz(lane * 8 + i)];
        v[4 * i + 0] = q.x; v[4 * i + 1] = q.y;
        v[4 * i + 2] = q.z; v[4 * i + 3] = q.w;
    }

    // ---- within-lane reduction tree (sums over 2,4,8,16,32 classes) ----
    float s2[16], s4[8], s8[4], s16[2], S;
#pragma unroll
    for (int i = 0; i < 16; i++) s2[i] = v[2 * i] + v[2 * i + 1];
#pragma unroll
    for (int i = 0; i < 8; i++)  s4[i] = s2[2 * i] + s2[2 * i + 1];
#pragma unroll
    for (int i = 0; i < 4; i++)  s8[i] = s4[2 * i] + s4[2 * i + 1];
#pragma unroll
    for (int i = 0; i < 2; i++)  s16[i] = s8[2 * i] + s8[2 * i + 1];
    S = s16[0] + s16[1];

    // ---- cross-lane levels: seg = 32, 64, 128, 256, 512 ----
    float F = 1.0f;
    {
        float o;
        o = __shfl_xor_sync(0xffffffffu, S, 1);
        F *= sigmoidf_fast((S - o) * (1.0f / 32.0f));  S += o;
        o = __shfl_xor_sync(0xffffffffu, S, 2);
        F *= sigmoidf_fast((S - o) * (1.0f / 64.0f));  S += o;
        o = __shfl_xor_sync(0xffffffffu, S, 4);
        F *= sigmoidf_fast((S - o) * (1.0f / 128.0f)); S += o;
        o = __shfl_xor_sync(0xffffffffu, S, 8);
        F *= sigmoidf_fast((S - o) * (1.0f / 256.0f)); S += o;
        o = __shfl_xor_sync(0xffffffffu, S, 16);
        F *= sigmoidf_fast((S - o) * (1.0f / 512.0f));
    }

    // ---- within-lane downsweep: seg = 16, 8, 4, 2, 1 ----
    float p16[2];
    {
        float a = sigmoidf_fast((s16[0] - s16[1]) * (1.0f / 16.0f));
        p16[0] = F * a;
        p16[1] = F - p16[0];
    }
    float p8[4];
#pragma unroll
    for (int i = 0; i < 2; i++) {
        float a = sigmoidf_fast((s8[2 * i] - s8[2 * i + 1]) * (1.0f / 8.0f));
        p8[2 * i] = p16[i] * a;
        p8[2 * i + 1] = p16[i] - p8[2 * i];
    }
    float p4[8];
#pragma unroll
    for (int i = 0; i < 4; i++) {
        float a = sigmoidf_fast((s4[2 * i] - s4[2 * i + 1]) * (1.0f / 4.0f));
        p4[2 * i] = p8[i] * a;
        p4[2 * i + 1] = p8[i] - p4[2 * i];
    }
    float p2[16];
#pragma unroll
    for (int i = 0; i < 8; i++) {
        float a = sigmoidf_fast((s2[2 * i] - s2[2 * i + 1]) * (1.0f / 2.0f));
        p2[2 * i] = p4[i] * a;
        p2[2 * i + 1] = p4[i] - p2[2 * i];
    }

    // leaves (seg=1) -> results, written back to smem swizzled
    __syncwarp();
#pragma unroll
    for (int i = 0; i < 8; i++) {
        float4 w;
        {
            float a = sigmoidf_fast(v[4 * i + 0] - v[4 * i + 1]);
            w.x = p2[2 * i] * a;
            w.y = p2[2 * i] - w.x;
        }
        {
            float a = sigmoidf_fast(v[4 * i + 2] - v[4 * i + 3]);
            w.z = p2[2 * i + 1] * a;
            w.w = p2[2 * i + 1] - w.z;
        }
        buf[wib][swz(lane * 8 + i)] = w;
    }
    __syncwarp();

    // ---- coalesced store from swizzled smem ----
    float4* gout = reinterpret_cast<float4*>(out + (size_t)row * NCLASS);
#pragma unroll
    for (int j = 0; j < 8; j++) {
        int c = j * 32 + lane;
        gout[j * 32 + lane] = buf[wib][swz(c)];
    }
}

extern "C" void kernel_launch(void* const* d_in, const int* in_sizes, int n_in,
                              void* d_out, int out_size) {
    (void)in_sizes; (void)n_in; (void)out_size;
    const float* in = (const float*)d_in[0];
    float* out = (float*)d_out;
    soft_tree_kernel<<<BATCH_N / WARPS_PER_BLOCK, WARPS_PER_BLOCK * 32>>>(in, out);
}